// round 12
// baseline (speedup 1.0000x reference)
#include <cuda_runtime.h>
#include <cuda_fp16.h>
#include <cstdint>

#define IN_F   3072
#define OUT_F  9216
#define RANK   32
#define KPAD   3104          // 3072 + 32 lora cols; 97 * 32
#define MROWS  4096
#define NCHUNK 97
#define TM     256
#define TN     128

__device__ __half g_A[(size_t)MROWS * KPAD];
__device__ __half g_B[(size_t)OUT_F * KPAD];

__device__ __forceinline__ uint32_t smem_u32(const void* p) {
    uint32_t a;
    asm("{ .reg .u64 t; cvta.to.shared.u64 t, %1; cvt.u32.u64 %0, t; }" : "=r"(a) : "l"(p));
    return a;
}
#define SWZ64(b) ((b) ^ (((b) >> 3) & 0x30))

#define CP16(sa, gp) \
    asm volatile("cp.async.cg.shared.global [%0], [%1], 16;" :: "r"(sa), "l"(gp))
#define CP_COMMIT() asm volatile("cp.async.commit_group;")
#define CP_WAIT0()  asm volatile("cp.async.wait_group 0;")
#define CP_WAIT1()  asm volatile("cp.async.wait_group 1;")

#define LDSM4(r0, r1, r2, r3, a) \
    asm volatile("ldmatrix.sync.aligned.m8n8.x4.shared.b16 {%0,%1,%2,%3}, [%4];" \
        : "=r"(r0), "=r"(r1), "=r"(r2), "=r"(r3) : "r"(a))

#define MMA16816(d, a, b0, b1) \
    asm volatile("mma.sync.aligned.m16n8k16.row.col.f32.f16.f16.f32 " \
        "{%0,%1,%2,%3}, {%4,%5,%6,%7}, {%8,%9}, {%0,%1,%2,%3};" \
        : "+f"((d)[0]), "+f"((d)[1]), "+f"((d)[2]), "+f"((d)[3]) \
        : "r"((a)[0]), "r"((a)[1]), "r"((a)[2]), "r"((a)[3]), "r"(b0), "r"(b1))

// ---------- kernel 1: fused activation group-quant + lora_act --------------
__global__ void __launch_bounds__(384) quant_act_kernel(
    const float* __restrict__ x, const float* __restrict__ smooth,
    const float* __restrict__ ldw)
{
    __shared__ float xs_s[IN_F];
    __shared__ float red[12][RANK];
    int m = blockIdx.x, t = threadIdx.x;
    const float4* xp = reinterpret_cast<const float4*>(x + (size_t)m * IN_F + t * 8);
    const float4* sp = reinterpret_cast<const float4*>(smooth + t * 8);
    float4 x0 = xp[0], x1 = xp[1], s0 = sp[0], s1 = sp[1];
    float xs[8];
    xs[0] = __fdiv_rn(x0.x, s0.x); xs[1] = __fdiv_rn(x0.y, s0.y);
    xs[2] = __fdiv_rn(x0.z, s0.z); xs[3] = __fdiv_rn(x0.w, s0.w);
    xs[4] = __fdiv_rn(x1.x, s1.x); xs[5] = __fdiv_rn(x1.y, s1.y);
    xs[6] = __fdiv_rn(x1.z, s1.z); xs[7] = __fdiv_rn(x1.w, s1.w);
    #pragma unroll
    for (int i = 0; i < 8; i++) xs_s[t * 8 + i] = xs[i];

    float am = 0.f;
    #pragma unroll
    for (int i = 0; i < 8; i++) am = fmaxf(am, fabsf(xs[i]));
    am = fmaxf(am, __shfl_xor_sync(~0u, am, 1));
    am = fmaxf(am, __shfl_xor_sync(~0u, am, 2));
    am = fmaxf(am, __shfl_xor_sync(~0u, am, 4));
    float ascale = fmaxf(__fdiv_rn(am, 7.0f), 1e-8f);
    union { uint4 u; __half h[8]; } o;
    #pragma unroll
    for (int i = 0; i < 8; i++) {
        float q = rintf(__fdiv_rn(xs[i], ascale));
        q = fminf(fmaxf(q, -8.f), 7.f);
        o.h[i] = __float2half_rn(q * ascale);
    }
    *reinterpret_cast<uint4*>(g_A + (size_t)m * KPAD + t * 8) = o.u;

    __syncthreads();
    int r = t & 31, slice = t >> 5;
    const float* lp = ldw + (size_t)(slice * 256) * RANK + r;
    const float* xp2 = xs_s + slice * 256;
    float acc = 0.f;
    #pragma unroll 8
    for (int k = 0; k < 256; k++) acc += xp2[k] * lp[(size_t)k * RANK];
    red[slice][r] = acc;
    __syncthreads();
    if (t < RANK) {
        float s = 0.f;
        #pragma unroll
        for (int j = 0; j < 12; j++) s += red[j][t];
        g_A[(size_t)m * KPAD + IN_F + t] = __float2half_rn(s);
    }
}

// ---------- kernel 2: weight int4 dequant (int32 input) -> fp16 ------------
__global__ void __launch_bounds__(256) wdeq_kernel(
    const int* __restrict__ qw, const float* __restrict__ ws)
{
    int tid = blockIdx.x * blockDim.x + threadIdx.x;
    if (tid >= OUT_F * 192) return;
    int n = tid / 192, c = tid - n * 192, k0 = c * 16;
    const int4* q4 = reinterpret_cast<const int4*>(qw + (size_t)n * (IN_F / 2) + c * 8);
    int4 v0 = q4[0], v1 = q4[1];
    int vals[8] = {v0.x, v0.y, v0.z, v0.w, v1.x, v1.y, v1.z, v1.w};
    float scale = ws[(k0 >> 6) * OUT_F + n];
    union { uint4 u[2]; __half h[16]; } o;
    #pragma unroll
    for (int j = 0; j < 8; j++) {
        int b  = vals[j];
        int lo = ((b & 15) ^ 8) - 8;
        int hi = b >> 4;
        o.h[2*j]   = __float2half_rn((float)lo * scale);
        o.h[2*j+1] = __float2half_rn((float)hi * scale);
    }
    uint4* dst = reinterpret_cast<uint4*>(g_B + (size_t)n * KPAD + k0);
    dst[0] = o.u[0]; dst[1] = o.u[1];
}

// ---------- kernel 3: lora_up -> B pad cols ---------------------------------
__global__ void __launch_bounds__(256) wlora_kernel(const float* __restrict__ lu)
{
    int n = blockIdx.x * blockDim.x + threadIdx.x;
    if (n >= OUT_F) return;
    const float4* src = reinterpret_cast<const float4*>(lu + (size_t)n * RANK);
    union { uint4 u[4]; __half h[32]; } o;
    #pragma unroll
    for (int i = 0; i < 8; i++) {
        float4 v = src[i];
        o.h[4*i+0] = __float2half_rn(v.x); o.h[4*i+1] = __float2half_rn(v.y);
        o.h[4*i+2] = __float2half_rn(v.z); o.h[4*i+3] = __float2half_rn(v.w);
    }
    uint4* dst = reinterpret_cast<uint4*>(g_B + (size_t)n * KPAD + IN_F);
    #pragma unroll
    for (int i = 0; i < 4; i++) dst[i] = o.u[i];
}

// ---------- kernel 4: mma.sync GEMM 256x128, 512 thr / 16 warps ------------
// warp grid 4M x 4N, warp tile 64x32, K-chunk 32, double-buffered cp.async.
__global__ void __launch_bounds__(512, 1) gemm_kernel(
    const float* __restrict__ bias, const float* __restrict__ nq,
    const float* __restrict__ nk,   const float* __restrict__ rope,
    float* __restrict__ out)
{
    __shared__ __align__(128) uint8_t smA[2][TM * 64];   // 2 x 16KB
    __shared__ __align__(128) uint8_t smB[2][TN * 64];   // 2 x 8KB
    float* ss_s = reinterpret_cast<float*>(smA);         // aliased post-mainloop

    int t = threadIdx.x, wid = t >> 5, lane = t & 31;
    int wm = wid >> 2, wn = wid & 3;
    int quad = lane >> 2, qlane = lane & 3;
    int n0 = blockIdx.x * TN, m0 = blockIdx.y * TM;

    uint32_t sbA = smem_u32(smA), sbB = smem_u32(smB);
    const __half* Ag = g_A + (size_t)m0 * KPAD;
    const __half* Bg = g_B + (size_t)n0 * KPAD;

    // A: 1024 16B segs (2/thread); B: 512 segs (1/thread)
    uint32_t soA[2], soB;
    size_t goA[2], goB;
    #pragma unroll
    for (int i = 0; i < 2; i++) {
        int seg = i * 512 + t, row = seg >> 2, s = seg & 3;
        soA[i] = SWZ64((uint32_t)(row * 64 + s * 16));
        goA[i] = (size_t)row * KPAD + s * 8;
    }
    {
        int row = t >> 2, s = t & 3;
        soB = SWZ64((uint32_t)(row * 64 + s * 16));
        goB = (size_t)row * KPAD + s * 8;
    }

    float acc[4][4][4];
    #pragma unroll
    for (int mi = 0; mi < 4; mi++)
        #pragma unroll
        for (int ni = 0; ni < 4; ni++)
            #pragma unroll
            for (int j = 0; j < 4; j++) acc[mi][ni][j] = 0.f;

    #pragma unroll
    for (int i = 0; i < 2; i++) CP16(sbA + soA[i], Ag + goA[i]);
    CP16(sbB + soB, Bg + goB);
    CP_COMMIT();

    int buf = 0;
    for (int kt = 0; kt < NCHUNK; kt++) {
        if (kt + 1 < NCHUNK) {
            uint32_t ab = sbA + (buf ^ 1) * (TM * 64);
            uint32_t bb = sbB + (buf ^ 1) * (TN * 64);
            int ko = (kt + 1) * 32;
            #pragma unroll
            for (int i = 0; i < 2; i++) CP16(ab + soA[i], Ag + goA[i] + ko);
            CP16(bb + soB, Bg + goB + ko);
            CP_COMMIT();
            CP_WAIT1();
        } else {
            CP_WAIT0();
        }
        __syncthreads();

        uint32_t aBase = sbA + buf * (TM * 64);
        uint32_t bBase = sbB + buf * (TN * 64);
        #pragma unroll
        for (int ks = 0; ks < 2; ks++) {
            uint32_t a[4][4];
            #pragma unroll
            for (int mi = 0; mi < 4; mi++) {
                int row = wm * 64 + mi * 16 + ((lane >> 3) & 1) * 8 + (lane & 7);
                int kh  = ks * 2 + (lane >> 4);
                LDSM4(a[mi][0], a[mi][1], a[mi][2], a[mi][3],
                      aBase + SWZ64((uint32_t)(row * 64 + kh * 16)));
            }
            uint32_t bf[2][4];
            #pragma unroll
            for (int nj = 0; nj < 2; nj++) {
                int row = wn * 32 + nj * 16 + ((lane >> 4) & 1) * 8 + (lane & 7);
                int kh  = ks * 2 + ((lane >> 3) & 1);
                LDSM4(bf[nj][0], bf[nj][1], bf[nj][2], bf[nj][3],
                      bBase + SWZ64((uint32_t)(row * 64 + kh * 16)));
            }
            #pragma unroll
            for (int mi = 0; mi < 4; mi++)
                #pragma unroll
                for (int ni = 0; ni < 4; ni++)
                    MMA16816(acc[mi][ni], a[mi],
                             bf[ni >> 1][(ni & 1) * 2], bf[ni >> 1][(ni & 1) * 2 + 1]);
        }
        __syncthreads();
        buf ^= 1;
    }

    // ---------------- fused epilogue ----------------
    int part = n0 / IN_F;     // 0=q, 1=k, 2=v (tile N == one head of 128)
    float bv[4][2];
    #pragma unroll
    for (int ni = 0; ni < 4; ni++) {
        int c = n0 + wn * 32 + ni * 8 + qlane * 2;
        bv[ni][0] = bias[c]; bv[ni][1] = bias[c + 1];
    }
    #pragma unroll
    for (int mi = 0; mi < 4; mi++)
        #pragma unroll
        for (int ni = 0; ni < 4; ni++) {
            acc[mi][ni][0] += bv[ni][0]; acc[mi][ni][1] += bv[ni][1];
            acc[mi][ni][2] += bv[ni][0]; acc[mi][ni][3] += bv[ni][1];
        }

    if (part < 2) {
        #pragma unroll
        for (int mi = 0; mi < 4; mi++) {
            float sl = 0.f, sh = 0.f;
            #pragma unroll
            for (int ni = 0; ni < 4; ni++) {
                sl += acc[mi][ni][0] * acc[mi][ni][0] + acc[mi][ni][1] * acc[mi][ni][1];
                sh += acc[mi][ni][2] * acc[mi][ni][2] + acc[mi][ni][3] * acc[mi][ni][3];
            }
            sl += __shfl_xor_sync(~0u, sl, 1); sl += __shfl_xor_sync(~0u, sl, 2);
            sh += __shfl_xor_sync(~0u, sh, 1); sh += __shfl_xor_sync(~0u, sh, 2);
            if (qlane == 0) {
                ss_s[(wm * 64 + mi * 16 + quad) * 4 + wn]     = sl;
                ss_s[(wm * 64 + mi * 16 + quad + 8) * 4 + wn] = sh;
            }
        }
    }
    __syncthreads();

    if (part < 2) {
        const float* g = part ? nk : nq;
        float gv[4][2];
        #pragma unroll
        for (int ni = 0; ni < 4; ni++) {
            int c = wn * 32 + ni * 8 + qlane * 2;
            gv[ni][0] = g[c]; gv[ni][1] = g[c + 1];
        }
        #pragma unroll
        for (int mi = 0; mi < 4; mi++) {
            int row = wm * 64 + mi * 16 + quad;
            float sl = ss_s[row * 4] + ss_s[row * 4 + 1] + ss_s[row * 4 + 2] + ss_s[row * 4 + 3];
            float sh = ss_s[(row + 8) * 4] + ss_s[(row + 8) * 4 + 1]
                     + ss_s[(row + 8) * 4 + 2] + ss_s[(row + 8) * 4 + 3];
            float rl = rsqrtf(sl * (1.0f / 128.0f) + 1e-6f);
            float rh = rsqrtf(sh * (1.0f / 128.0f) + 1e-6f);
            int m = m0 + row;
            #pragma unroll
            for (int ni = 0; ni < 4; ni++) {
                int col = wn * 32 + ni * 8 + qlane * 2;
                float e0 = acc[mi][ni][0] * rl * gv[ni][0];
                float o0 = acc[mi][ni][1] * rl * gv[ni][1];
                float2 cs = *reinterpret_cast<const float2*>(rope + (size_t)m * 128 + col);
                acc[mi][ni][0] = e0 * cs.x - o0 * cs.y;
                acc[mi][ni][1] = e0 * cs.y + o0 * cs.x;
                float e1 = acc[mi][ni][2] * rh * gv[ni][0];
                float o1 = acc[mi][ni][3] * rh * gv[ni][1];
                float2 cs2 = *reinterpret_cast<const float2*>(rope + (size_t)(m + 8) * 128 + col);
                acc[mi][ni][2] = e1 * cs2.x - o1 * cs2.y;
                acc[mi][ni][3] = e1 * cs2.y + o1 * cs2.x;
            }
        }
    }

    #pragma unroll
    for (int mi = 0; mi < 4; mi++) {
        int row = wm * 64 + mi * 16 + quad;
        size_t m = m0 + row;
        #pragma unroll
        for (int ni = 0; ni < 4; ni++) {
            int col = n0 + wn * 32 + ni * 8 + qlane * 2;
            float2 v0 = make_float2(acc[mi][ni][0], acc[mi][ni][1]);
            float2 v1 = make_float2(acc[mi][ni][2], acc[mi][ni][3]);
            *reinterpret_cast<float2*>(out + m * OUT_F + col) = v0;
            *reinterpret_cast<float2*>(out + (m + 8) * OUT_F + col) = v1;
        }
    }
}

extern "C" void kernel_launch(void* const* d_in, const int* in_sizes, int n_in,
                              void* d_out, int out_size) {
    const float *x = 0, *ws = 0, *bias = 0, *ldw = 0, *lu = 0, *smooth = 0;
    const float *nq = 0, *nk = 0, *rope = 0;
    const int* qw = 0;
    for (int i = 0; i < n_in; i++) {
        long s = in_sizes[i];
        const void* p = d_in[i];
        if      (s == 12582912) x      = (const float*)p;
        else if (s == 14155776) qw     = (const int*)p;     // int8 widened to int32
        else if (s == 442368)   ws     = (const float*)p;
        else if (s == 9216)     bias   = (const float*)p;
        else if (s == 98304)    ldw    = (const float*)p;
        else if (s == 294912)   lu     = (const float*)p;
        else if (s == 3072)     smooth = (const float*)p;
        else if (s == 524288)   rope   = (const float*)p;
        else if (s == 128)      { if (!nq) nq = (const float*)p; else nk = (const float*)p; }
    }
    float* out = (float*)d_out;

    quant_act_kernel<<<MROWS, 384>>>(x, smooth, ldw);
    wdeq_kernel<<<(OUT_F * 192 + 255) / 256, 256>>>(qw, ws);
    wlora_kernel<<<(OUT_F + 255) / 256, 256>>>(lu);
    gemm_kernel<<<dim3(OUT_F / TN, MROWS / TM), 512>>>(bias, nq, nk, rope, out);
}

// round 13
// speedup vs baseline: 1.1815x; 1.1815x over previous
#include <cuda_runtime.h>
#include <cuda_fp16.h>
#include <cstdint>

#define IN_F   3072
#define OUT_F  9216
#define RANK   32
#define KPAD   3104          // 3072 + 32 lora cols; 97 * 32
#define MROWS  4096
#define NCHUNK 97
#define TM     128
#define TN     128

__device__ __half g_A[(size_t)MROWS * KPAD];
__device__ __half g_B[(size_t)OUT_F * KPAD];

__device__ __forceinline__ uint32_t smem_u32(const void* p) {
    uint32_t a;
    asm("{ .reg .u64 t; cvta.to.shared.u64 t, %1; cvt.u32.u64 %0, t; }" : "=r"(a) : "l"(p));
    return a;
}
#define SWZ64(b) ((b) ^ (((b) >> 3) & 0x30))

#define CP16(sa, gp) \
    asm volatile("cp.async.cg.shared.global [%0], [%1], 16;" :: "r"(sa), "l"(gp))
#define CP_COMMIT() asm volatile("cp.async.commit_group;")
#define CP_WAIT0()  asm volatile("cp.async.wait_group 0;")
#define CP_WAIT1()  asm volatile("cp.async.wait_group 1;")

#define LDSM4(r0, r1, r2, r3, a) \
    asm volatile("ldmatrix.sync.aligned.m8n8.x4.shared.b16 {%0,%1,%2,%3}, [%4];" \
        : "=r"(r0), "=r"(r1), "=r"(r2), "=r"(r3) : "r"(a))

#define MMA16816(d, a, b0, b1) \
    asm volatile("mma.sync.aligned.m16n8k16.row.col.f32.f16.f16.f32 " \
        "{%0,%1,%2,%3}, {%4,%5,%6,%7}, {%8,%9}, {%0,%1,%2,%3};" \
        : "+f"((d)[0]), "+f"((d)[1]), "+f"((d)[2]), "+f"((d)[3]) \
        : "r"((a)[0]), "r"((a)[1]), "r"((a)[2]), "r"((a)[3]), "r"(b0), "r"(b1))

// ---------- kernel 1: fused activation group-quant + lora_act --------------
__global__ void __launch_bounds__(384) quant_act_kernel(
    const float* __restrict__ x, const float* __restrict__ smooth,
    const float* __restrict__ ldw)
{
    __shared__ float xs_s[IN_F];
    __shared__ float red[12][RANK];
    int m = blockIdx.x, t = threadIdx.x;
    const float4* xp = reinterpret_cast<const float4*>(x + (size_t)m * IN_F + t * 8);
    const float4* sp = reinterpret_cast<const float4*>(smooth + t * 8);
    float4 x0 = xp[0], x1 = xp[1], s0 = sp[0], s1 = sp[1];
    float xs[8];
    xs[0] = __fdiv_rn(x0.x, s0.x); xs[1] = __fdiv_rn(x0.y, s0.y);
    xs[2] = __fdiv_rn(x0.z, s0.z); xs[3] = __fdiv_rn(x0.w, s0.w);
    xs[4] = __fdiv_rn(x1.x, s1.x); xs[5] = __fdiv_rn(x1.y, s1.y);
    xs[6] = __fdiv_rn(x1.z, s1.z); xs[7] = __fdiv_rn(x1.w, s1.w);
    #pragma unroll
    for (int i = 0; i < 8; i++) xs_s[t * 8 + i] = xs[i];

    float am = 0.f;
    #pragma unroll
    for (int i = 0; i < 8; i++) am = fmaxf(am, fabsf(xs[i]));
    am = fmaxf(am, __shfl_xor_sync(~0u, am, 1));
    am = fmaxf(am, __shfl_xor_sync(~0u, am, 2));
    am = fmaxf(am, __shfl_xor_sync(~0u, am, 4));
    float ascale = fmaxf(__fdiv_rn(am, 7.0f), 1e-8f);
    union { uint4 u; __half h[8]; } o;
    #pragma unroll
    for (int i = 0; i < 8; i++) {
        float q = rintf(__fdiv_rn(xs[i], ascale));
        q = fminf(fmaxf(q, -8.f), 7.f);
        o.h[i] = __float2half_rn(q * ascale);
    }
    *reinterpret_cast<uint4*>(g_A + (size_t)m * KPAD + t * 8) = o.u;

    __syncthreads();
    int r = t & 31, slice = t >> 5;
    const float* lp = ldw + (size_t)(slice * 256) * RANK + r;
    const float* xp2 = xs_s + slice * 256;
    float acc = 0.f;
    #pragma unroll 8
    for (int k = 0; k < 256; k++) acc += xp2[k] * lp[(size_t)k * RANK];
    red[slice][r] = acc;
    __syncthreads();
    if (t < RANK) {
        float s = 0.f;
        #pragma unroll
        for (int j = 0; j < 12; j++) s += red[j][t];
        g_A[(size_t)m * KPAD + IN_F + t] = __float2half_rn(s);
    }
}

// ---------- kernel 2: weight int4 dequant (int32 input) -> fp16 ------------
__global__ void __launch_bounds__(256) wdeq_kernel(
    const int* __restrict__ qw, const float* __restrict__ ws)
{
    int tid = blockIdx.x * blockDim.x + threadIdx.x;
    if (tid >= OUT_F * 192) return;
    int n = tid / 192, c = tid - n * 192, k0 = c * 16;
    const int4* q4 = reinterpret_cast<const int4*>(qw + (size_t)n * (IN_F / 2) + c * 8);
    int4 v0 = q4[0], v1 = q4[1];
    int vals[8] = {v0.x, v0.y, v0.z, v0.w, v1.x, v1.y, v1.z, v1.w};
    float scale = ws[(k0 >> 6) * OUT_F + n];
    union { uint4 u[2]; __half h[16]; } o;
    #pragma unroll
    for (int j = 0; j < 8; j++) {
        int b  = vals[j];
        int lo = ((b & 15) ^ 8) - 8;
        int hi = b >> 4;
        o.h[2*j]   = __float2half_rn((float)lo * scale);
        o.h[2*j+1] = __float2half_rn((float)hi * scale);
    }
    uint4* dst = reinterpret_cast<uint4*>(g_B + (size_t)n * KPAD + k0);
    dst[0] = o.u[0]; dst[1] = o.u[1];
}

// ---------- kernel 3: lora_up -> B pad cols ---------------------------------
__global__ void __launch_bounds__(256) wlora_kernel(const float* __restrict__ lu)
{
    int n = blockIdx.x * blockDim.x + threadIdx.x;
    if (n >= OUT_F) return;
    const float4* src = reinterpret_cast<const float4*>(lu + (size_t)n * RANK);
    union { uint4 u[4]; __half h[32]; } o;
    #pragma unroll
    for (int i = 0; i < 8; i++) {
        float4 v = src[i];
        o.h[4*i+0] = __float2half_rn(v.x); o.h[4*i+1] = __float2half_rn(v.y);
        o.h[4*i+2] = __float2half_rn(v.z); o.h[4*i+3] = __float2half_rn(v.w);
    }
    uint4* dst = reinterpret_cast<uint4*>(g_B + (size_t)n * KPAD + IN_F);
    #pragma unroll
    for (int i = 0; i < 4; i++) dst[i] = o.u[i];
}

// ---------- kernel 4: mma.sync GEMM 128x128, 2 CTAs/SM ----------------------
// 256 thr, 8 warps (2M x 4N), warp tile 64x32, K-chunk 32, double-buffered.
__global__ void __launch_bounds__(256, 2) gemm_kernel(
    const float* __restrict__ bias, const float* __restrict__ nq,
    const float* __restrict__ nk,   const float* __restrict__ rope,
    float* __restrict__ out)
{
    __shared__ __align__(128) uint8_t smA[2][TM * 64];   // 2 x 8KB
    __shared__ __align__(128) uint8_t smB[2][TN * 64];   // 2 x 8KB
    __shared__ float ss_s[TM][4];

    int t = threadIdx.x, wid = t >> 5, lane = t & 31;
    int wm = wid >> 2, wn = wid & 3;
    int quad = lane >> 2, qlane = lane & 3;
    int n0 = blockIdx.x * TN, m0 = blockIdx.y * TM;

    uint32_t sbA = smem_u32(smA), sbB = smem_u32(smB);
    const __half* Ag = g_A + (size_t)m0 * KPAD;
    const __half* Bg = g_B + (size_t)n0 * KPAD;

    // A: 512 16B segs (2/thread); B: 512 segs (2/thread)
    int r0 = t >> 2, s0 = t & 3;
    int r1 = (t + 256) >> 2, s1 = t & 3;
    uint32_t so0 = SWZ64((uint32_t)(r0 * 64 + s0 * 16));
    uint32_t so1 = SWZ64((uint32_t)(r1 * 64 + s1 * 16));
    size_t go0 = (size_t)r0 * KPAD + s0 * 8;
    size_t go1 = (size_t)r1 * KPAD + s1 * 8;

    float acc[4][4][4];
    #pragma unroll
    for (int mi = 0; mi < 4; mi++)
        #pragma unroll
        for (int ni = 0; ni < 4; ni++)
            #pragma unroll
            for (int j = 0; j < 4; j++) acc[mi][ni][j] = 0.f;

    CP16(sbA + so0, Ag + go0);
    CP16(sbA + so1, Ag + go1);
    CP16(sbB + so0, Bg + go0);
    CP16(sbB + so1, Bg + go1);
    CP_COMMIT();

    int buf = 0;
    for (int kt = 0; kt < NCHUNK; kt++) {
        if (kt + 1 < NCHUNK) {
            uint32_t ab = sbA + (buf ^ 1) * (TM * 64);
            uint32_t bb = sbB + (buf ^ 1) * (TN * 64);
            int ko = (kt + 1) * 32;
            CP16(ab + so0, Ag + go0 + ko);
            CP16(ab + so1, Ag + go1 + ko);
            CP16(bb + so0, Bg + go0 + ko);
            CP16(bb + so1, Bg + go1 + ko);
            CP_COMMIT();
            CP_WAIT1();
        } else {
            CP_WAIT0();
        }
        __syncthreads();

        uint32_t aBase = sbA + buf * (TM * 64);
        uint32_t bBase = sbB + buf * (TN * 64);
        #pragma unroll
        for (int ks = 0; ks < 2; ks++) {
            uint32_t a[4][4];
            #pragma unroll
            for (int mi = 0; mi < 4; mi++) {
                int row = wm * 64 + mi * 16 + ((lane >> 3) & 1) * 8 + (lane & 7);
                int kh  = ks * 2 + (lane >> 4);
                LDSM4(a[mi][0], a[mi][1], a[mi][2], a[mi][3],
                      aBase + SWZ64((uint32_t)(row * 64 + kh * 16)));
            }
            uint32_t bf[2][4];
            #pragma unroll
            for (int nj = 0; nj < 2; nj++) {
                int row = wn * 32 + nj * 16 + ((lane >> 4) & 1) * 8 + (lane & 7);
                int kh  = ks * 2 + ((lane >> 3) & 1);
                LDSM4(bf[nj][0], bf[nj][1], bf[nj][2], bf[nj][3],
                      bBase + SWZ64((uint32_t)(row * 64 + kh * 16)));
            }
            #pragma unroll
            for (int mi = 0; mi < 4; mi++)
                #pragma unroll
                for (int ni = 0; ni < 4; ni++)
                    MMA16816(acc[mi][ni], a[mi],
                             bf[ni >> 1][(ni & 1) * 2], bf[ni >> 1][(ni & 1) * 2 + 1]);
        }
        __syncthreads();
        buf ^= 1;
    }

    // ---------------- fused epilogue ----------------
    int part = n0 / IN_F;     // 0=q, 1=k, 2=v (tile N == one head of 128)
    float bv[4][2];
    #pragma unroll
    for (int ni = 0; ni < 4; ni++) {
        int c = n0 + wn * 32 + ni * 8 + qlane * 2;
        bv[ni][0] = bias[c]; bv[ni][1] = bias[c + 1];
    }
    #pragma unroll
    for (int mi = 0; mi < 4; mi++)
        #pragma unroll
        for (int ni = 0; ni < 4; ni++) {
            acc[mi][ni][0] += bv[ni][0]; acc[mi][ni][1] += bv[ni][1];
            acc[mi][ni][2] += bv[ni][0]; acc[mi][ni][3] += bv[ni][1];
        }

    if (part < 2) {
        #pragma unroll
        for (int mi = 0; mi < 4; mi++) {
            float sl = 0.f, sh = 0.f;
            #pragma unroll
            for (int ni = 0; ni < 4; ni++) {
                sl += acc[mi][ni][0] * acc[mi][ni][0] + acc[mi][ni][1] * acc[mi][ni][1];
                sh += acc[mi][ni][2] * acc[mi][ni][2] + acc[mi][ni][3] * acc[mi][ni][3];
            }
            sl += __shfl_xor_sync(~0u, sl, 1); sl += __shfl_xor_sync(~0u, sl, 2);
            sh += __shfl_xor_sync(~0u, sh, 1); sh += __shfl_xor_sync(~0u, sh, 2);
            if (qlane == 0) {
                ss_s[wm * 64 + mi * 16 + quad][wn]     = sl;
                ss_s[wm * 64 + mi * 16 + quad + 8][wn] = sh;
            }
        }
    }
    __syncthreads();

    if (part < 2) {
        const float* g = part ? nk : nq;
        float gv[4][2];
        #pragma unroll
        for (int ni = 0; ni < 4; ni++) {
            int c = wn * 32 + ni * 8 + qlane * 2;
            gv[ni][0] = g[c]; gv[ni][1] = g[c + 1];
        }
        #pragma unroll
        for (int mi = 0; mi < 4; mi++) {
            int row = wm * 64 + mi * 16 + quad;
            float sl = ss_s[row][0] + ss_s[row][1] + ss_s[row][2] + ss_s[row][3];
            float sh = ss_s[row + 8][0] + ss_s[row + 8][1] + ss_s[row + 8][2] + ss_s[row + 8][3];
            float rl = rsqrtf(sl * (1.0f / 128.0f) + 1e-6f);
            float rh = rsqrtf(sh * (1.0f / 128.0f) + 1e-6f);
            int m = m0 + row;
            #pragma unroll
            for (int ni = 0; ni < 4; ni++) {
                int col = wn * 32 + ni * 8 + qlane * 2;
                float e0 = acc[mi][ni][0] * rl * gv[ni][0];
                float o0 = acc[mi][ni][1] * rl * gv[ni][1];
                float2 cs = *reinterpret_cast<const float2*>(rope + (size_t)m * 128 + col);
                acc[mi][ni][0] = e0 * cs.x - o0 * cs.y;
                acc[mi][ni][1] = e0 * cs.y + o0 * cs.x;
                float e1 = acc[mi][ni][2] * rh * gv[ni][0];
                float o1 = acc[mi][ni][3] * rh * gv[ni][1];
                float2 cs2 = *reinterpret_cast<const float2*>(rope + (size_t)(m + 8) * 128 + col);
                acc[mi][ni][2] = e1 * cs2.x - o1 * cs2.y;
                acc[mi][ni][3] = e1 * cs2.y + o1 * cs2.x;
            }
        }
    }

    #pragma unroll
    for (int mi = 0; mi < 4; mi++) {
        int row = wm * 64 + mi * 16 + quad;
        size_t m = m0 + row;
        #pragma unroll
        for (int ni = 0; ni < 4; ni++) {
            int col = n0 + wn * 32 + ni * 8 + qlane * 2;
            float2 v0 = make_float2(acc[mi][ni][0], acc[mi][ni][1]);
            float2 v1 = make_float2(acc[mi][ni][2], acc[mi][ni][3]);
            *reinterpret_cast<float2*>(out + m * OUT_F + col) = v0;
            *reinterpret_cast<float2*>(out + (m + 8) * OUT_F + col) = v1;
        }
    }
}

extern "C" void kernel_launch(void* const* d_in, const int* in_sizes, int n_in,
                              void* d_out, int out_size) {
    const float *x = 0, *ws = 0, *bias = 0, *ldw = 0, *lu = 0, *smooth = 0;
    const float *nq = 0, *nk = 0, *rope = 0;
    const int* qw = 0;
    for (int i = 0; i < n_in; i++) {
        long s = in_sizes[i];
        const void* p = d_in[i];
        if      (s == 12582912) x      = (const float*)p;
        else if (s == 14155776) qw     = (const int*)p;     // int8 widened to int32
        else if (s == 442368)   ws     = (const float*)p;
        else if (s == 9216)     bias   = (const float*)p;
        else if (s == 98304)    ldw    = (const float*)p;
        else if (s == 294912)   lu     = (const float*)p;
        else if (s == 3072)     smooth = (const float*)p;
        else if (s == 524288)   rope   = (const float*)p;
        else if (s == 128)      { if (!nq) nq = (const float*)p; else nk = (const float*)p; }
    }
    float* out = (float*)d_out;

    quant_act_kernel<<<MROWS, 384>>>(x, smooth, ldw);
    wdeq_kernel<<<(OUT_F * 192 + 255) / 256, 256>>>(qw, ws);
    wlora_kernel<<<(OUT_F + 255) / 256, 256>>>(lu);
    gemm_kernel<<<dim3(OUT_F / TN, MROWS / TM), 256>>>(bias, nq, nk, rope, out);
}

// round 14
// speedup vs baseline: 1.3048x; 1.1043x over previous
#include <cuda_runtime.h>
#include <cuda_fp16.h>
#include <cstdint>

#define IN_F   3072
#define OUT_F  9216
#define RANK   32
#define KPAD   3136          // 49 * 64 ; lora at 3072..3103, zero pad to 3136
#define MROWS  4096
#define NCHUNK 49
#define TM     128
#define TN     128
#define STG    16384         // bytes per A (or B) stage: 128 rows x 128B

__device__ __half g_A[(size_t)MROWS * KPAD];
__device__ __half g_B[(size_t)OUT_F * KPAD];

__device__ __forceinline__ uint32_t smem_u32(const void* p) {
    uint32_t a;
    asm("{ .reg .u64 t; cvta.to.shared.u64 t, %1; cvt.u32.u64 %0, t; }" : "=r"(a) : "l"(p));
    return a;
}
#define SWZ128(b) ((b) ^ (((b) >> 3) & 0x70))

#define CP16(sa, gp) \
    asm volatile("cp.async.cg.shared.global [%0], [%1], 16;" :: "r"(sa), "l"(gp))
#define CP_COMMIT() asm volatile("cp.async.commit_group;")
#define CP_WAIT0()  asm volatile("cp.async.wait_group 0;")
#define CP_WAIT1()  asm volatile("cp.async.wait_group 1;")

#define LDSM4(r0, r1, r2, r3, a) \
    asm volatile("ldmatrix.sync.aligned.m8n8.x4.shared.b16 {%0,%1,%2,%3}, [%4];" \
        : "=r"(r0), "=r"(r1), "=r"(r2), "=r"(r3) : "r"(a))

#define MMA16816(d, a, b0, b1) \
    asm volatile("mma.sync.aligned.m16n8k16.row.col.f32.f16.f16.f32 " \
        "{%0,%1,%2,%3}, {%4,%5,%6,%7}, {%8,%9}, {%0,%1,%2,%3};" \
        : "+f"((d)[0]), "+f"((d)[1]), "+f"((d)[2]), "+f"((d)[3]) \
        : "r"((a)[0]), "r"((a)[1]), "r"((a)[2]), "r"((a)[3]), "r"(b0), "r"(b1))

// ---------- kernel 1: fused activation group-quant + lora_act --------------
__global__ void __launch_bounds__(384) quant_act_kernel(
    const float* __restrict__ x, const float* __restrict__ smooth,
    const float* __restrict__ ldw)
{
    __shared__ float xs_s[IN_F];
    __shared__ float red[12][RANK];
    int m = blockIdx.x, t = threadIdx.x;
    const float4* xp = reinterpret_cast<const float4*>(x + (size_t)m * IN_F + t * 8);
    const float4* sp = reinterpret_cast<const float4*>(smooth + t * 8);
    float4 x0 = xp[0], x1 = xp[1], s0 = sp[0], s1 = sp[1];
    float xs[8];
    xs[0] = __fdiv_rn(x0.x, s0.x); xs[1] = __fdiv_rn(x0.y, s0.y);
    xs[2] = __fdiv_rn(x0.z, s0.z); xs[3] = __fdiv_rn(x0.w, s0.w);
    xs[4] = __fdiv_rn(x1.x, s1.x); xs[5] = __fdiv_rn(x1.y, s1.y);
    xs[6] = __fdiv_rn(x1.z, s1.z); xs[7] = __fdiv_rn(x1.w, s1.w);
    #pragma unroll
    for (int i = 0; i < 8; i++) xs_s[t * 8 + i] = xs[i];

    float am = 0.f;
    #pragma unroll
    for (int i = 0; i < 8; i++) am = fmaxf(am, fabsf(xs[i]));
    am = fmaxf(am, __shfl_xor_sync(~0u, am, 1));
    am = fmaxf(am, __shfl_xor_sync(~0u, am, 2));
    am = fmaxf(am, __shfl_xor_sync(~0u, am, 4));
    float ascale = fmaxf(__fdiv_rn(am, 7.0f), 1e-8f);
    union { uint4 u; __half h[8]; } o;
    #pragma unroll
    for (int i = 0; i < 8; i++) {
        float q = rintf(__fdiv_rn(xs[i], ascale));
        q = fminf(fmaxf(q, -8.f), 7.f);
        o.h[i] = __float2half_rn(q * ascale);
    }
    *reinterpret_cast<uint4*>(g_A + (size_t)m * KPAD + t * 8) = o.u;

    __syncthreads();
    int r = t & 31, slice = t >> 5;
    const float* lp = ldw + (size_t)(slice * 256) * RANK + r;
    const float* xp2 = xs_s + slice * 256;
    float acc = 0.f;
    #pragma unroll 8
    for (int k = 0; k < 256; k++) acc += xp2[k] * lp[(size_t)k * RANK];
    red[slice][r] = acc;
    __syncthreads();
    if (t < RANK) {
        float s = 0.f;
        #pragma unroll
        for (int j = 0; j < 12; j++) s += red[j][t];
        g_A[(size_t)m * KPAD + IN_F + t] = __float2half_rn(s);
        g_A[(size_t)m * KPAD + IN_F + RANK + t] = __float2half_rn(0.f);
    }
}

// ---------- kernel 2: weight int4 dequant (int32 input) -> fp16 ------------
__global__ void __launch_bounds__(256) wdeq_kernel(
    const int* __restrict__ qw, const float* __restrict__ ws)
{
    int tid = blockIdx.x * blockDim.x + threadIdx.x;
    if (tid >= OUT_F * 192) return;
    int n = tid / 192, c = tid - n * 192, k0 = c * 16;
    const int4* q4 = reinterpret_cast<const int4*>(qw + (size_t)n * (IN_F / 2) + c * 8);
    int4 v0 = q4[0], v1 = q4[1];
    int vals[8] = {v0.x, v0.y, v0.z, v0.w, v1.x, v1.y, v1.z, v1.w};
    float scale = ws[(k0 >> 6) * OUT_F + n];
    union { uint4 u[2]; __half h[16]; } o;
    #pragma unroll
    for (int j = 0; j < 8; j++) {
        int b  = vals[j];
        int lo = ((b & 15) ^ 8) - 8;
        int hi = b >> 4;
        o.h[2*j]   = __float2half_rn((float)lo * scale);
        o.h[2*j+1] = __float2half_rn((float)hi * scale);
    }
    uint4* dst = reinterpret_cast<uint4*>(g_B + (size_t)n * KPAD + k0);
    dst[0] = o.u[0]; dst[1] = o.u[1];
}

// ---------- kernel 3: lora_up -> B pad cols (with zero tail) ----------------
__global__ void __launch_bounds__(256) wlora_kernel(const float* __restrict__ lu)
{
    int n = blockIdx.x * blockDim.x + threadIdx.x;
    if (n >= OUT_F) return;
    const float4* src = reinterpret_cast<const float4*>(lu + (size_t)n * RANK);
    union { uint4 u[4]; __half h[32]; } o;
    #pragma unroll
    for (int i = 0; i < 8; i++) {
        float4 v = src[i];
        o.h[4*i+0] = __float2half_rn(v.x); o.h[4*i+1] = __float2half_rn(v.y);
        o.h[4*i+2] = __float2half_rn(v.z); o.h[4*i+3] = __float2half_rn(v.w);
    }
    uint4* dst = reinterpret_cast<uint4*>(g_B + (size_t)n * KPAD + IN_F);
    uint4 z = make_uint4(0, 0, 0, 0);
    #pragma unroll
    for (int i = 0; i < 4; i++) dst[i] = o.u[i];
    #pragma unroll
    for (int i = 4; i < 8; i++) dst[i] = z;
}

// ---------- kernel 4: mma.sync GEMM 128x128, K-chunk 64, 2 CTAs/SM ----------
__global__ void __launch_bounds__(256, 2) gemm_kernel(
    const float* __restrict__ bias, const float* __restrict__ nq,
    const float* __restrict__ nk,   const float* __restrict__ rope,
    float* __restrict__ out)
{
    extern __shared__ __align__(128) uint8_t dsm[];   // [2][STG] A | [2][STG] B
    float* ss_s = reinterpret_cast<float*>(dsm);      // aliased post-mainloop

    int t = threadIdx.x, wid = t >> 5, lane = t & 31;
    int wm = wid >> 2, wn = wid & 3;
    int quad = lane >> 2, qlane = lane & 3;
    int n0 = blockIdx.x * TN, m0 = blockIdx.y * TM;

    uint32_t sbA = smem_u32(dsm), sbB = sbA + 2 * STG;
    const __half* Ag = g_A + (size_t)m0 * KPAD;
    const __half* Bg = g_B + (size_t)n0 * KPAD;

    // tile = 128 rows x 128B = 1024 16B segs; 4 per thread for A and B
    uint32_t so[4];
    size_t go[4];
    #pragma unroll
    for (int i = 0; i < 4; i++) {
        int seg = i * 256 + t, row = seg >> 3, s = seg & 7;
        so[i] = SWZ128((uint32_t)(row * 128 + s * 16));
        go[i] = (size_t)row * KPAD + s * 8;
    }

    float acc[4][4][4];
    #pragma unroll
    for (int mi = 0; mi < 4; mi++)
        #pragma unroll
        for (int ni = 0; ni < 4; ni++)
            #pragma unroll
            for (int j = 0; j < 4; j++) acc[mi][ni][j] = 0.f;

    #pragma unroll
    for (int i = 0; i < 4; i++) CP16(sbA + so[i], Ag + go[i]);
    #pragma unroll
    for (int i = 0; i < 4; i++) CP16(sbB + so[i], Bg + go[i]);
    CP_COMMIT();

    int buf = 0;
    for (int kt = 0; kt < NCHUNK; kt++) {
        if (kt + 1 < NCHUNK) {
            uint32_t ab = sbA + (buf ^ 1) * STG;
            uint32_t bb = sbB + (buf ^ 1) * STG;
            int ko = (kt + 1) * 64;
            #pragma unroll
            for (int i = 0; i < 4; i++) CP16(ab + so[i], Ag + go[i] + ko);
            #pragma unroll
            for (int i = 0; i < 4; i++) CP16(bb + so[i], Bg + go[i] + ko);
            CP_COMMIT();
            CP_WAIT1();
        } else {
            CP_WAIT0();
        }
        __syncthreads();

        uint32_t aBase = sbA + buf * STG;
        uint32_t bBase = sbB + buf * STG;
        #pragma unroll
        for (int ks = 0; ks < 4; ks++) {
            uint32_t a[4][4];
            #pragma unroll
            for (int mi = 0; mi < 4; mi++) {
                int row = wm * 64 + mi * 16 + ((lane >> 3) & 1) * 8 + (lane & 7);
                int kh  = ks * 2 + (lane >> 4);
                LDSM4(a[mi][0], a[mi][1], a[mi][2], a[mi][3],
                      aBase + SWZ128((uint32_t)(row * 128 + kh * 16)));
            }
            uint32_t bf[2][4];
            #pragma unroll
            for (int nj = 0; nj < 2; nj++) {
                int row = wn * 32 + nj * 16 + ((lane >> 4) & 1) * 8 + (lane & 7);
                int kh  = ks * 2 + ((lane >> 3) & 1);
                LDSM4(bf[nj][0], bf[nj][1], bf[nj][2], bf[nj][3],
                      bBase + SWZ128((uint32_t)(row * 128 + kh * 16)));
            }
            #pragma unroll
            for (int mi = 0; mi < 4; mi++)
                #pragma unroll
                for (int ni = 0; ni < 4; ni++)
                    MMA16816(acc[mi][ni], a[mi],
                             bf[ni >> 1][(ni & 1) * 2], bf[ni >> 1][(ni & 1) * 2 + 1]);
        }
        __syncthreads();
        buf ^= 1;
    }

    // ---------------- fused epilogue ----------------
    int part = n0 / IN_F;     // 0=q, 1=k, 2=v (tile N == one head of 128)
    float bv[4][2];
    #pragma unroll
    for (int ni = 0; ni < 4; ni++) {
        int c = n0 + wn * 32 + ni * 8 + qlane * 2;
        bv[ni][0] = bias[c]; bv[ni][1] = bias[c + 1];
    }
    #pragma unroll
    for (int mi = 0; mi < 4; mi++)
        #pragma unroll
        for (int ni = 0; ni < 4; ni++) {
            acc[mi][ni][0] += bv[ni][0]; acc[mi][ni][1] += bv[ni][1];
            acc[mi][ni][2] += bv[ni][0]; acc[mi][ni][3] += bv[ni][1];
        }

    if (part < 2) {
        #pragma unroll
        for (int mi = 0; mi < 4; mi++) {
            float sl = 0.f, sh = 0.f;
            #pragma unroll
            for (int ni = 0; ni < 4; ni++) {
                sl += acc[mi][ni][0] * acc[mi][ni][0] + acc[mi][ni][1] * acc[mi][ni][1];
                sh += acc[mi][ni][2] * acc[mi][ni][2] + acc[mi][ni][3] * acc[mi][ni][3];
            }
            sl += __shfl_xor_sync(~0u, sl, 1); sl += __shfl_xor_sync(~0u, sl, 2);
            sh += __shfl_xor_sync(~0u, sh, 1); sh += __shfl_xor_sync(~0u, sh, 2);
            if (qlane == 0) {
                ss_s[(wm * 64 + mi * 16 + quad) * 4 + wn]     = sl;
                ss_s[(wm * 64 + mi * 16 + quad + 8) * 4 + wn] = sh;
            }
        }
    }
    __syncthreads();

    if (part < 2) {
        const float* g = part ? nk : nq;
        float gv[4][2];
        #pragma unroll
        for (int ni = 0; ni < 4; ni++) {
            int c = wn * 32 + ni * 8 + qlane * 2;
            gv[ni][0] = g[c]; gv[ni][1] = g[c + 1];
        }
        #pragma unroll
        for (int mi = 0; mi < 4; mi++) {
            int row = wm * 64 + mi * 16 + quad;
            float sl = ss_s[row * 4] + ss_s[row * 4 + 1] + ss_s[row * 4 + 2] + ss_s[row * 4 + 3];
            float sh = ss_s[(row + 8) * 4] + ss_s[(row + 8) * 4 + 1]
                     + ss_s[(row + 8) * 4 + 2] + ss_s[(row + 8) * 4 + 3];
            float rl = rsqrtf(sl * (1.0f / 128.0f) + 1e-6f);
            float rh = rsqrtf(sh * (1.0f / 128.0f) + 1e-6f);
            int m = m0 + row;
            #pragma unroll
            for (int ni = 0; ni < 4; ni++) {
                int col = wn * 32 + ni * 8 + qlane * 2;
                float e0 = acc[mi][ni][0] * rl * gv[ni][0];
                float o0 = acc[mi][ni][1] * rl * gv[ni][1];
                float2 cs = *reinterpret_cast<const float2*>(rope + (size_t)m * 128 + col);
                acc[mi][ni][0] = e0 * cs.x - o0 * cs.y;
                acc[mi][ni][1] = e0 * cs.y + o0 * cs.x;
                float e1 = acc[mi][ni][2] * rh * gv[ni][0];
                float o1 = acc[mi][ni][3] * rh * gv[ni][1];
                float2 cs2 = *reinterpret_cast<const float2*>(rope + (size_t)(m + 8) * 128 + col);
                acc[mi][ni][2] = e1 * cs2.x - o1 * cs2.y;
                acc[mi][ni][3] = e1 * cs2.y + o1 * cs2.x;
            }
        }
    }

    #pragma unroll
    for (int mi = 0; mi < 4; mi++) {
        int row = wm * 64 + mi * 16 + quad;
        size_t m = m0 + row;
        #pragma unroll
        for (int ni = 0; ni < 4; ni++) {
            int col = n0 + wn * 32 + ni * 8 + qlane * 2;
            float2 v0 = make_float2(acc[mi][ni][0], acc[mi][ni][1]);
            float2 v1 = make_float2(acc[mi][ni][2], acc[mi][ni][3]);
            *reinterpret_cast<float2*>(out + m * OUT_F + col) = v0;
            *reinterpret_cast<float2*>(out + (m + 8) * OUT_F + col) = v1;
        }
    }
}

extern "C" void kernel_launch(void* const* d_in, const int* in_sizes, int n_in,
                              void* d_out, int out_size) {
    const float *x = 0, *ws = 0, *bias = 0, *ldw = 0, *lu = 0, *smooth = 0;
    const float *nq = 0, *nk = 0, *rope = 0;
    const int* qw = 0;
    for (int i = 0; i < n_in; i++) {
        long s = in_sizes[i];
        const void* p = d_in[i];
        if      (s == 12582912) x      = (const float*)p;
        else if (s == 14155776) qw     = (const int*)p;     // int8 widened to int32
        else if (s == 442368)   ws     = (const float*)p;
        else if (s == 9216)     bias   = (const float*)p;
        else if (s == 98304)    ldw    = (const float*)p;
        else if (s == 294912)   lu     = (const float*)p;
        else if (s == 3072)     smooth = (const float*)p;
        else if (s == 524288)   rope   = (const float*)p;
        else if (s == 128)      { if (!nq) nq = (const float*)p; else nk = (const float*)p; }
    }
    float* out = (float*)d_out;

    static bool attr_set = false;
    if (!attr_set) {
        cudaFuncSetAttribute(gemm_kernel,
            cudaFuncAttributeMaxDynamicSharedMemorySize, 4 * STG);
        attr_set = true;
    }

    quant_act_kernel<<<MROWS, 384>>>(x, smooth, ldw);
    wdeq_kernel<<<(OUT_F * 192 + 255) / 256, 256>>>(qw, ws);
    wlora_kernel<<<(OUT_F + 255) / 256, 256>>>(lu);
    gemm_kernel<<<dim3(OUT_F / TN, MROWS / TM), 256, 4 * STG>>>(bias, nq, nk, rope, out);
}